// round 6
// baseline (speedup 1.0000x reference)
#include <cuda_runtime.h>
#include <cuda_bf16.h>
#include <cstddef>
#include <cstdint>

typedef unsigned long long ull;

#define RNN_B 32
#define RNN_T 512
#define RNN_E 1024
#define RNN_H 1024
#define RNN_M (RNN_B * RNN_T)

#define NBLK 128            // persistent grid (<=148 SMs -> co-resident)
#define JPB 8               // output columns per block
#define SCAN_THREADS 512
#define NW 16               // warps per scan block
#define K2_PER_WARP (RNN_H / 2 / NW)   // 32 k-pairs per warp
#define HDEPTH 4            // h ring-buffer depth

// Device scratch
__device__ float g_xp[RNN_M * RNN_H];          // 64 MB: x @ W_ih^T + bias
__device__ float g_h2[HDEPTH][RNN_H * RNN_B];  // pair-interleaved h ring
__device__ int      g_ready[NBLK];             // latest step published per block
__device__ unsigned g_rdone[RNN_T];            // blocks done READING h_t

// ---------------- f32x2 packed helpers -------------------------------------
__device__ __forceinline__ ull pack2(float x, float y) {
    ull r; asm("mov.b64 %0,{%1,%2};" : "=l"(r) : "f"(x), "f"(y)); return r;
}
__device__ __forceinline__ void ffma2(ull& d, ull a, ull b) {
    asm("fma.rn.f32x2 %0,%1,%2,%0;" : "+l"(d) : "l"(a), "l"(b));
}
__device__ __forceinline__ float2 unpack2(ull v) {
    float lo, hi; asm("mov.b64 {%0,%1},%2;" : "=f"(lo), "=f"(hi) : "l"(v));
    return make_float2(lo, hi);
}

// ---------------------------------------------------------------------------
// xp = x @ W_ih^T + (b_ih + b_hh). 64x64x16 tiles, 4x4/thread, FFMA2 inner.
// Block (0,0) also resets the scan's flag state (runs before scan in stream
// order, so every graph replay starts clean).
// ---------------------------------------------------------------------------
#define BM 64
#define BN 64
#define BK 16

__global__ __launch_bounds__(256) void xp_gemm(
    const float* __restrict__ x,
    const float* __restrict__ Wih,
    const float* __restrict__ bih,
    const float* __restrict__ bhh)
{
    __shared__ float As[BK][BM];
    __shared__ float Bs[BK][BN];

    const int bm = blockIdx.y * BM;
    const int bn = blockIdx.x * BN;
    const int tid = threadIdx.x;

    if (bm == 0 && bn == 0) {                 // reset dataflow state
        if (tid < NBLK) g_ready[tid] = -1;
        for (int i = tid; i < RNN_T; i += 256) g_rdone[i] = 0u;
    }

    const int tm = (tid / 16) * 4;
    const int tn = (tid % 16) * 4;
    const int lr = tid / 4;
    const int lk = (tid % 4) * 4;

    const float* Aptr = x   + (size_t)(bm + lr) * RNN_E;
    const float* Bptr = Wih + (size_t)(bn + lr) * RNN_E;

    ull accp[4][2] = {};

    for (int k0 = 0; k0 < RNN_E; k0 += BK) {
        float4 av = *(const float4*)(Aptr + k0 + lk);
        float4 bv = *(const float4*)(Bptr + k0 + lk);
        As[lk + 0][lr] = av.x; As[lk + 1][lr] = av.y;
        As[lk + 2][lr] = av.z; As[lk + 3][lr] = av.w;
        Bs[lk + 0][lr] = bv.x; Bs[lk + 1][lr] = bv.y;
        Bs[lk + 2][lr] = bv.z; Bs[lk + 3][lr] = bv.w;
        __syncthreads();

        #pragma unroll
        for (int k = 0; k < BK; k++) {
            float4 a4 = *(const float4*)&As[k][tm];
            float4 b4 = *(const float4*)&Bs[k][tn];
            ull bp0 = pack2(b4.x, b4.y);
            ull bp1 = pack2(b4.z, b4.w);
            float a[4] = {a4.x, a4.y, a4.z, a4.w};
            #pragma unroll
            for (int i = 0; i < 4; i++) {
                ull ad = pack2(a[i], a[i]);
                ffma2(accp[i][0], ad, bp0);
                ffma2(accp[i][1], ad, bp1);
            }
        }
        __syncthreads();
    }

    float bias[4];
    #pragma unroll
    for (int j = 0; j < 4; j++)
        bias[j] = bih[bn + tn + j] + bhh[bn + tn + j];

    #pragma unroll
    for (int i = 0; i < 4; i++) {
        float2 f0 = unpack2(accp[i][0]);
        float2 f1 = unpack2(accp[i][1]);
        float4 v = make_float4(f0.x + bias[0], f0.y + bias[1],
                               f1.x + bias[2], f1.y + bias[3]);
        *(float4*)&g_xp[(size_t)(bm + tm + i) * RNN_H + bn + tn] = v;
    }
}

// ---------------------------------------------------------------------------
// Dataflow scan. 128 blocks x 512 thr. Block p owns j in [8p, 8p+8).
// Warp w consumes k-pairs [w*32, w*32+32)  <- produced by blocks 8w..8w+7.
// No grid barrier: warps hot-spin on the 8 per-block ready flags they need.
// h crosses steps via a depth-4 pair-interleaved ring; writer of h_t checks
// that h_{t-4} (same slot) has been read by all blocks (g_rdone), which is
// 3 steps stale and almost never blocks.
// ---------------------------------------------------------------------------
__global__ __launch_bounds__(SCAN_THREADS) void rnn_scan(
    const float* __restrict__ Whh,
    float* __restrict__ out)
{
    __shared__ ull   sw[RNN_H / 2][JPB];       // 32 KB weights
    __shared__ float red[NW][RNN_B * 9];       // partials, padded stride 9

    const int tid  = threadIdx.x;
    const int w    = tid >> 5;
    const int lane = tid & 31;
    const int blk  = blockIdx.x;
    const int j0   = blk * JPB;

    // Load weight slice as packed k-pairs (coalesced over k2).
    for (int idx = tid; idx < (RNN_H / 2) * JPB; idx += SCAN_THREADS) {
        int jj = idx >> 9;
        int k2 = idx & (RNN_H / 2 - 1);
        sw[k2][jj] = *(const ull*)&Whh[(size_t)(j0 + jj) * RNN_H + 2 * k2];
    }
    __syncthreads();

    const int rjj = tid & 7;
    const int rb  = tid >> 3;                  // valid when tid < 256

    // ---- t = 0: h = tanh(xp) ----
    if (tid < 256) {
        const size_t m = (size_t)rb * RNN_T;
        float v = tanhf(__ldcs(&g_xp[m * RNN_H + j0 + rjj]));
        out[m * RNN_H + j0 + rjj] = v;
        int j = j0 + rjj;
        __stcg(&g_h2[0][(j >> 1) * 64 + rb * 2 + (j & 1)], v);
    }
    __threadfence();
    __syncthreads();
    if (tid == 0) *(volatile int*)&g_ready[blk] = 0;

    const int k2lo  = w * K2_PER_WARP;
    const int pbase = w * 8;                   // my 8 producer blocks
    const int pq    = pbase + (lane & 7);      // flag this lane polls

    for (int t = 1; t < RNN_T; t++) {
        // prefetch xp (independent of flags / h)
        float xpv = 0.0f;
        if (tid < 256)
            xpv = __ldcs(&g_xp[((size_t)rb * RNN_T + t) * RNN_H + j0 + rjj]);

        // wait for h_{t-1} producers (hot spin, no nanosleep)
        const int need = t - 1;
        while (*(volatile const int*)&g_ready[pq] < need) {}
        __syncwarp();
        __threadfence();                        // order flag read before h loads

        const ull* __restrict__ hp = (const ull*)g_h2[(t - 1) & (HDEPTH - 1)];

        ull acc[JPB] = {};
        #pragma unroll 4
        for (int k2 = k2lo; k2 < k2lo + K2_PER_WARP; k2++) {
            ull hv = __ldcg(&hp[k2 * 32 + lane]);
            const ull* wr = sw[k2];
            ulonglong2 q0 = *(const ulonglong2*)&wr[0];
            ulonglong2 q1 = *(const ulonglong2*)&wr[2];
            ulonglong2 q2 = *(const ulonglong2*)&wr[4];
            ulonglong2 q3 = *(const ulonglong2*)&wr[6];
            ffma2(acc[0], hv, q0.x); ffma2(acc[1], hv, q0.y);
            ffma2(acc[2], hv, q1.x); ffma2(acc[3], hv, q1.y);
            ffma2(acc[4], hv, q2.x); ffma2(acc[5], hv, q2.y);
            ffma2(acc[6], hv, q3.x); ffma2(acc[7], hv, q3.y);
        }

        #pragma unroll
        for (int jj = 0; jj < JPB; jj++) {
            float2 f = unpack2(acc[jj]);
            red[w][lane * 9 + jj] = f.x + f.y;
        }
        __syncthreads();   // #1: all h loads landed, partials visible

        // ack our reads of h_{t-1}; check ring-slot hazard for h_t
        if (tid == 0) {
            atomicAdd(&g_rdone[t - 1], 1u);
            if (t >= HDEPTH && t < RNN_T - 1) {
                while (*(volatile const unsigned*)&g_rdone[t - HDEPTH] < NBLK) {}
            }
        }
        __syncthreads();   // #2: hazard cleared for everyone

        if (tid < 256) {
            float s = xpv;
            #pragma unroll
            for (int w2 = 0; w2 < NW; w2++)
                s += red[w2][rb * 9 + rjj];
            float hn = tanhf(s);
            out[((size_t)rb * RNN_T + t) * RNN_H + j0 + rjj] = hn;
            if (t < RNN_T - 1) {
                int j = j0 + rjj;
                __stcg(&g_h2[t & (HDEPTH - 1)][(j >> 1) * 64 + rb * 2 + (j & 1)], hn);
            }
        }

        if (t < RNN_T - 1) {
            __threadfence();      // all writers: make h visible
            __syncthreads();      // #3: every writer fenced
            if (tid == 0) *(volatile int*)&g_ready[blk] = t;   // publish
        }
    }
}

// ---------------------------------------------------------------------------
extern "C" void kernel_launch(void* const* d_in, const int* in_sizes, int n_in,
                              void* d_out, int out_size) {
    const float* x    = (const float*)d_in[0];
    const float* W_ih = (const float*)d_in[1];
    const float* W_hh = (const float*)d_in[2];
    const float* b_ih = (const float*)d_in[3];
    const float* b_hh = (const float*)d_in[4];
    float* out = (float*)d_out;

    (void)in_sizes; (void)n_in; (void)out_size;

    xp_gemm<<<dim3(RNN_H / BN, RNN_M / BM), 256>>>(x, W_ih, b_ih, b_hh);
    rnn_scan<<<NBLK, SCAN_THREADS>>>(W_hh, out);
}